// round 14
// baseline (speedup 1.0000x reference)
#include <cuda_runtime.h>
#include <cuda_bf16.h>
#include <cstdint>

// Problem constants
#define OBS 64
#define ACTD 8
#define DDIM 256
#define SDIM 32
#define HDIM 256
#define BSZ 1024
#define TSTEPS 128
#define TMPN 1280          // D(prior) + D(post-h) + 3D(gru)
#define OUTW 416           // D + 5*S
#define NROWS (BSZ*TSTEPS) // 131072

// ---------------- device scratch ----------------
__device__ float g_tmp[BSZ * TMPN];                     // per-step GEMM out
__device__ float g_q1e[(size_t)NROWS * HDIM];           // fp32 posterior emb-side preact
__device__ __nv_bfloat16 g_Ah[BSZ * 768];               // h split [hi|hi|lo] (scan)
__device__ __nv_bfloat16 g_Wcat[TMPN * 768];            // [Wp1;Wq1h;Whh] split (scan)
// MLP weights, hi/lo pairs
__device__ __nv_bfloat16 g_W1hi[256 * 64],  g_W1lo[256 * 64];
__device__ __nv_bfloat16 g_W2hi[256 * 256], g_W2lo[256 * 256];
__device__ __nv_bfloat16 g_W3hi[256 * 256], g_W3lo[256 * 256];

// group barrier state: 8 strips, each on its own 128B line
__device__ unsigned g_grp_cnt[8 * 32];
__device__ volatile unsigned g_grp_gen[8 * 32];

// ---------------- split helpers ----------------
__device__ __forceinline__ void split_bf16(float x, __nv_bfloat16& hi, __nv_bfloat16& lo) {
    hi = __float2bfloat16_rn(x);
    lo = __float2bfloat16_rn(x - __bfloat162float(hi));
}

// ---------------- single fused pack kernel ----------------
#define PK0 65536
#define PK1 65536
#define PK2 196608
#define PK3 16384
#define PK4 65536
#define PK5 65536
#define PKTOT (PK0+PK1+PK2+PK3+PK4+PK5)

__global__ void pack_all_kernel(const float* __restrict__ Wp1,
                                const float* __restrict__ Wq1,
                                const float* __restrict__ Whh,
                                const float* __restrict__ We1,
                                const float* __restrict__ We2)
{
    int idx = blockIdx.x * blockDim.x + threadIdx.x;
    if (idx >= PKTOT) return;
    if (idx < PK0 + PK1 + PK2) {
        int j, k;
        float w;
        int rbase;
        if (idx < PK0) {
            j = idx >> 8; k = idx & 255; rbase = 0;
            w = Wp1[j * 256 + k];
        } else if (idx < PK0 + PK1) {
            int i2 = idx - PK0;
            j = i2 >> 8; k = i2 & 255; rbase = 256;
            w = Wq1[(size_t)j * 512 + k];
        } else {
            int i2 = idx - PK0 - PK1;
            j = i2 >> 8; k = i2 & 255; rbase = 512;
            w = Whh[(size_t)j * 256 + k];
        }
        __nv_bfloat16 hi, lo; split_bf16(w, hi, lo);
        __nv_bfloat16* d = g_Wcat + (size_t)(rbase + j) * 768;
        d[k] = hi; d[256 + k] = lo; d[512 + k] = hi;
    } else {
        int i2 = idx - (PK0 + PK1 + PK2);
        float w;
        __nv_bfloat16 *dhi, *dlo;
        int off;
        if (i2 < PK3) {
            int j = i2 >> 6, k = i2 & 63;
            w = We1[j * 64 + k]; dhi = g_W1hi; dlo = g_W1lo; off = i2;
        } else if (i2 < PK3 + PK4) {
            int i3 = i2 - PK3;
            int j = i3 >> 8, k = i3 & 255;
            w = We2[j * 256 + k]; dhi = g_W2hi; dlo = g_W2lo; off = i3;
        } else {
            int i3 = i2 - PK3 - PK4;
            int j = i3 >> 8, k = i3 & 255;
            w = Wq1[(size_t)j * 512 + 256 + k]; dhi = g_W3hi; dlo = g_W3lo; off = i3;
        }
        __nv_bfloat16 hi, lo; split_bf16(w, hi, lo);
        dhi[off] = hi; dlo[off] = lo;
    }
}

// ---------------- mma helpers ----------------
__device__ __forceinline__ void mma_bf16(float* c, const uint32_t* a, const uint32_t* b) {
    asm volatile(
        "mma.sync.aligned.m16n8k16.row.col.f32.bf16.bf16.f32 "
        "{%0,%1,%2,%3}, {%4,%5,%6,%7}, {%8,%9}, {%0,%1,%2,%3};\n"
        : "+f"(c[0]), "+f"(c[1]), "+f"(c[2]), "+f"(c[3])
        : "r"(a[0]), "r"(a[1]), "r"(a[2]), "r"(a[3]), "r"(b[0]), "r"(b[1]));
}

__device__ __forceinline__ uint32_t smem_u32(const void* p) {
    return (uint32_t)__cvta_generic_to_shared(p);
}
__device__ __forceinline__ void cp16(void* dst, const void* src) {
    asm volatile("cp.async.cg.shared.global [%0], [%1], 16;\n"
                 :: "r"(smem_u32(dst)), "l"(src));
}
__device__ __forceinline__ void cp_commit() { asm volatile("cp.async.commit_group;\n"); }
template <int N>
__device__ __forceinline__ void cp_wait() { asm volatile("cp.async.wait_group %0;\n"::"n"(N)); }

// ================= fused precompute MLP kernel (unchanged) =================
#define MRM 64
#define SA 264
#define SW 72
#define MS_AH 0
#define MS_AL (MRM * SA * 2)
#define MS_W  (2 * MRM * SA * 2)
#define MS_WPART (256 * SW * 2)
#define MS_TOTAL (MS_W + 4 * MS_WPART)

__device__ __forceinline__ void mma_tiles3(
    const __nv_bfloat16* AH, const __nv_bfloat16* AL,
    const __nv_bfloat16* WH, const __nv_bfloat16* WL,
    int kbase, int wm, int wn, int gid, int tg,
    float (*acc)[8][4])
{
#pragma unroll
    for (int kt = 0; kt < 4; kt++) {
        const int ka = kbase + kt * 16 + tg * 2;
        const int kw = kt * 16 + tg * 2;
        uint32_t ah[2][4], al[2][4];
#pragma unroll
        for (int mf = 0; mf < 2; mf++) {
            const int R = wm * 32 + mf * 16 + gid;
            ah[mf][0] = *(const uint32_t*)(&AH[R * SA + ka]);
            ah[mf][1] = *(const uint32_t*)(&AH[(R + 8) * SA + ka]);
            ah[mf][2] = *(const uint32_t*)(&AH[R * SA + ka + 8]);
            ah[mf][3] = *(const uint32_t*)(&AH[(R + 8) * SA + ka + 8]);
            al[mf][0] = *(const uint32_t*)(&AL[R * SA + ka]);
            al[mf][1] = *(const uint32_t*)(&AL[(R + 8) * SA + ka]);
            al[mf][2] = *(const uint32_t*)(&AL[R * SA + ka + 8]);
            al[mf][3] = *(const uint32_t*)(&AL[(R + 8) * SA + ka + 8]);
        }
#pragma unroll
        for (int nf = 0; nf < 8; nf++) {
            const int C = wn * 64 + nf * 8 + gid;
            uint32_t bh[2], bl[2];
            bh[0] = *(const uint32_t*)(&WH[C * SW + kw]);
            bh[1] = *(const uint32_t*)(&WH[C * SW + kw + 8]);
            bl[0] = *(const uint32_t*)(&WL[C * SW + kw]);
            bl[1] = *(const uint32_t*)(&WL[C * SW + kw + 8]);
#pragma unroll
            for (int mf = 0; mf < 2; mf++) {
                mma_bf16(acc[mf][nf], ah[mf], bh);
                mma_bf16(acc[mf][nf], ah[mf], bl);
                mma_bf16(acc[mf][nf], al[mf], bh);
            }
        }
    }
}

__device__ __forceinline__ void issue_wchunk(
    char* sm, int stage, int tid,
    const __nv_bfloat16* Ghi, const __nv_bfloat16* Glo, int gld, int kofs)
{
    __nv_bfloat16* WH = (__nv_bfloat16*)(sm + MS_W + (stage * 2 + 0) * MS_WPART);
    __nv_bfloat16* WL = (__nv_bfloat16*)(sm + MS_W + (stage * 2 + 1) * MS_WPART);
#pragma unroll
    for (int j = 0; j < 8; j++) {
        int idx = tid + j * 256;
        int n = idx >> 3, kk = (idx & 7) * 8;
        cp16(&WH[n * SW + kk], &Ghi[(size_t)n * gld + kofs + kk]);
        cp16(&WL[n * SW + kk], &Glo[(size_t)n * gld + kofs + kk]);
    }
    cp_commit();
}

__global__ __launch_bounds__(256, 1) void mlp_kernel(
    const float* __restrict__ obs,
    const float* __restrict__ be1,
    const float* __restrict__ be2,
    const float* __restrict__ bq1,
    float* __restrict__ q1e)
{
    extern __shared__ char sm[];
    __nv_bfloat16* AH = (__nv_bfloat16*)(sm + MS_AH);
    __nv_bfloat16* AL = (__nv_bfloat16*)(sm + MS_AL);

    const int tid = threadIdx.x;
    const int lane = tid & 31;
    const int warp = tid >> 5;
    const int gid = lane >> 2;
    const int tg = lane & 3;
    const int wm = warp & 1;
    const int wn = warp >> 1;
    const size_t row0 = (size_t)blockIdx.x * MRM;

    float acc[2][8][4];

    for (int i = tid; i < MRM * OBS; i += 256) {
        int r = i >> 6, c = i & 63;
        float v = obs[(row0 + r) * OBS + c];
        __nv_bfloat16 hi, lo; split_bf16(v, hi, lo);
        AH[r * SA + c] = hi; AL[r * SA + c] = lo;
    }
    {
        __nv_bfloat16* WH = (__nv_bfloat16*)(sm + MS_W + 0 * MS_WPART);
        __nv_bfloat16* WL = (__nv_bfloat16*)(sm + MS_W + 1 * MS_WPART);
#pragma unroll
        for (int j = 0; j < 8; j++) {
            int idx = tid + j * 256;
            int n = idx >> 3, kk = (idx & 7) * 8;
            cp16(&WH[n * SW + kk], &g_W1hi[n * 64 + kk]);
            cp16(&WL[n * SW + kk], &g_W1lo[n * 64 + kk]);
        }
        cp_commit();
    }
    cp_wait<0>();
    __syncthreads();

#pragma unroll
    for (int mf = 0; mf < 2; mf++)
#pragma unroll
        for (int nf = 0; nf < 8; nf++)
#pragma unroll
            for (int q = 0; q < 4; q++) acc[mf][nf][q] = 0.f;
    mma_tiles3(AH, AL,
               (__nv_bfloat16*)(sm + MS_W + 0 * MS_WPART),
               (__nv_bfloat16*)(sm + MS_W + 1 * MS_WPART),
               0, wm, wn, gid, tg, acc);
    __syncthreads();
#pragma unroll
    for (int mf = 0; mf < 2; mf++)
#pragma unroll
        for (int nf = 0; nf < 8; nf++) {
            const int R = wm * 32 + mf * 16 + gid;
            const int C = wn * 64 + nf * 8 + tg * 2;
            float b0 = be1[C], b1 = be1[C + 1];
            float v0 = acc[mf][nf][0] + b0, v1 = acc[mf][nf][1] + b1;
            float v2 = acc[mf][nf][2] + b0, v3 = acc[mf][nf][3] + b1;
            v0 = v0 > 0.f ? v0 : expm1f(v0);
            v1 = v1 > 0.f ? v1 : expm1f(v1);
            v2 = v2 > 0.f ? v2 : expm1f(v2);
            v3 = v3 > 0.f ? v3 : expm1f(v3);
            __nv_bfloat16 h0, l0, h1, l1, h2, l2, h3, l3;
            split_bf16(v0, h0, l0); split_bf16(v1, h1, l1);
            split_bf16(v2, h2, l2); split_bf16(v3, h3, l3);
            *(__nv_bfloat162*)(&AH[R * SA + C])       = __nv_bfloat162(h0, h1);
            *(__nv_bfloat162*)(&AL[R * SA + C])       = __nv_bfloat162(l0, l1);
            *(__nv_bfloat162*)(&AH[(R + 8) * SA + C]) = __nv_bfloat162(h2, h3);
            *(__nv_bfloat162*)(&AL[(R + 8) * SA + C]) = __nv_bfloat162(l2, l3);
        }
    __syncthreads();

    for (int layer = 0; layer < 2; layer++) {
        const __nv_bfloat16* Ghi = layer == 0 ? g_W2hi : g_W3hi;
        const __nv_bfloat16* Glo = layer == 0 ? g_W2lo : g_W3lo;
        const float* bias = layer == 0 ? be2 : bq1;

#pragma unroll
        for (int mf = 0; mf < 2; mf++)
#pragma unroll
            for (int nf = 0; nf < 8; nf++)
#pragma unroll
                for (int q = 0; q < 4; q++) acc[mf][nf][q] = 0.f;

        issue_wchunk(sm, 0, tid, Ghi, Glo, 256, 0);
        for (int c = 0; c < 4; c++) {
            if (c + 1 < 4) {
                issue_wchunk(sm, (c + 1) & 1, tid, Ghi, Glo, 256, (c + 1) * 64);
                cp_wait<1>();
            } else {
                cp_wait<0>();
            }
            __syncthreads();
            mma_tiles3(AH, AL,
                       (__nv_bfloat16*)(sm + MS_W + ((c & 1) * 2 + 0) * MS_WPART),
                       (__nv_bfloat16*)(sm + MS_W + ((c & 1) * 2 + 1) * MS_WPART),
                       c * 64, wm, wn, gid, tg, acc);
            __syncthreads();
        }

        if (layer == 0) {
#pragma unroll
            for (int mf = 0; mf < 2; mf++)
#pragma unroll
                for (int nf = 0; nf < 8; nf++) {
                    const int R = wm * 32 + mf * 16 + gid;
                    const int C = wn * 64 + nf * 8 + tg * 2;
                    float b0 = bias[C], b1 = bias[C + 1];
                    float v0 = acc[mf][nf][0] + b0, v1 = acc[mf][nf][1] + b1;
                    float v2 = acc[mf][nf][2] + b0, v3 = acc[mf][nf][3] + b1;
                    v0 = v0 > 0.f ? v0 : expm1f(v0);
                    v1 = v1 > 0.f ? v1 : expm1f(v1);
                    v2 = v2 > 0.f ? v2 : expm1f(v2);
                    v3 = v3 > 0.f ? v3 : expm1f(v3);
                    __nv_bfloat16 h0, l0, h1, l1, h2, l2, h3, l3;
                    split_bf16(v0, h0, l0); split_bf16(v1, h1, l1);
                    split_bf16(v2, h2, l2); split_bf16(v3, h3, l3);
                    *(__nv_bfloat162*)(&AH[R * SA + C])       = __nv_bfloat162(h0, h1);
                    *(__nv_bfloat162*)(&AL[R * SA + C])       = __nv_bfloat162(l0, l1);
                    *(__nv_bfloat162*)(&AH[(R + 8) * SA + C]) = __nv_bfloat162(h2, h3);
                    *(__nv_bfloat162*)(&AL[(R + 8) * SA + C]) = __nv_bfloat162(l2, l3);
                }
            __syncthreads();
        } else {
#pragma unroll
            for (int mf = 0; mf < 2; mf++)
#pragma unroll
                for (int nf = 0; nf < 8; nf++) {
                    const int R = wm * 32 + mf * 16 + gid;
                    const int C = wn * 64 + nf * 8 + tg * 2;
                    float b0 = bias[C], b1 = bias[C + 1];
                    *(float2*)(&q1e[(row0 + R) * 256 + C]) =
                        make_float2(acc[mf][nf][0] + b0, acc[mf][nf][1] + b1);
                    *(float2*)(&q1e[(row0 + R + 8) * 256 + C]) =
                        make_float2(acc[mf][nf][2] + b0, acc[mf][nf][3] + b1);
                }
        }
    }
}

// ================= persistent scan kernel =================
#define NBLK 128
#define WSLICE 80
#define WPAD 776
// phase-G A pipeline: chunks of 96 cols, TRIPLE-buffered
#define CHK 96
#define NCHK 8           // 768 / 96
#define APAD 104         // A chunk row stride (bf16): 52 words, conflict-free
#define ACHUNK (128 * APAD)  // 13312 elements per buffer

#define SM_W    0
#define SM_AS   (WSLICE * WPAD * 2)                  // 124160
#define SM_PQ   (SM_AS + 3 * ACHUNK * 2)             // +79872 = 204032
#define SM_ST   (SM_PQ + 2 * 8 * 256 * 4)            // +16384 = 220416
#define SM_ZA   (SM_ST + 8 * 128 * 4)                // +4096  = 224512
#define SM_TOTAL (SM_ZA + 8 * 40 * 4)                // +1280  = 225792

__device__ __forceinline__ float sigmf(float x) { return 1.f / (1.f + expf(-x)); }

// 16-block group barrier for strip s
__device__ __forceinline__ void group_sync(int s) {
    __syncthreads();
    if (threadIdx.x == 0) {
        __threadfence();
        unsigned* cnt = &g_grp_cnt[s * 32];
        volatile unsigned* gen = &g_grp_gen[s * 32];
        unsigned g = *gen;
        unsigned arrived = atomicAdd(cnt, 1u);
        if (arrived == 15u) {
            *cnt = 0u;
            __threadfence();
            *gen = g + 1u;
        } else {
            while (*gen == g) { }
        }
        __threadfence();
    }
    __syncthreads();
}

// issue cp.async load of one 128x96 A chunk into buffer buf (0..2)
__device__ __forceinline__ void issue_achunk(char* smraw, int buf, int tid,
                                             int mbase, int kofs)
{
    __nv_bfloat16* dst = (__nv_bfloat16*)(smraw + SM_AS) + buf * ACHUNK;
#pragma unroll
    for (int j = 0; j < 6; j++) {
        int idx = j * 256 + tid;          // 0..1535
        int row = idx / 12, cc = idx % 12;
        cp16(&dst[row * APAD + cc * 8],
             &g_Ah[(size_t)(mbase + row) * 768 + kofs + cc * 8]);
    }
    cp_commit();
}

__global__ __launch_bounds__(256, 1) void scan_kernel(
    const float* __restrict__ q1e,
    const float* __restrict__ noise,
    const float* __restrict__ act,
    const float* __restrict__ Wp2, const float* __restrict__ bp2,
    const float* __restrict__ Wq2, const float* __restrict__ bq2,
    const float* __restrict__ bp1,
    const float* __restrict__ Wih, const float* __restrict__ bih,
    const float* __restrict__ bhh,
    float* __restrict__ out)
{
    extern __shared__ char smraw[];
    __nv_bfloat16* Wsm = (__nv_bfloat16*)(smraw + SM_W);
    float* PQ = (float*)(smraw + SM_PQ);
    float* ST = (float*)(smraw + SM_ST);
    float* ZA = (float*)(smraw + SM_ZA);

    const int tid = threadIdx.x;
    const int blk = blockIdx.x;
    const int lane = tid & 31;
    const int warp = tid >> 5;
    const int gid = lane >> 2;
    const int tg = lane & 3;
    const int wm = warp & 3;
    const int wn = warp >> 2;
    const int bs = blk >> 4;
    const int cs = blk & 15;
    const int mbase = bs * 128;
    const int nbase = cs * WSLICE;
    const int b0 = blk * 8;

    for (int i = tid; i < WSLICE * 768; i += 256) {
        int r = i / 768, k = i - r * 768;
        Wsm[r * WPAD + k] = g_Wcat[(size_t)(nbase + r) * 768 + k];
    }
    __syncthreads();

    // persistent h state for this block's own 8 rows (thread tid owns dim d=tid)
    float hreg[8];
#pragma unroll
    for (int r = 0; r < 8; r++) hreg[r] = 0.f;

    for (int t = 0; t < TSTEPS; t++) {
        // ======== phase G: tmp = h_split @ Wslice^T (3-buffer cp.async pipeline) ========
        {
            float acc[2][5][4];
#pragma unroll
            for (int i = 0; i < 2; i++)
#pragma unroll
                for (int j = 0; j < 5; j++)
#pragma unroll
                    for (int q = 0; q < 4; q++) acc[i][j][q] = 0.f;

            issue_achunk(smraw, 0, tid, mbase, 0);
            issue_achunk(smraw, 1, tid, mbase, CHK);
#pragma unroll 1
            for (int c = 0; c < NCHK; c++) {
                if (c < NCHK - 1) { cp_wait<1>(); } else { cp_wait<0>(); }
                __syncthreads();      // chunk c visible; chunk c-1 fully consumed
                if (c + 2 < NCHK)
                    issue_achunk(smraw, (c + 2) % 3, tid, mbase, (c + 2) * CHK);

                const __nv_bfloat16* A =
                    (const __nv_bfloat16*)(smraw + SM_AS) + (c % 3) * ACHUNK;
#pragma unroll
                for (int kt = 0; kt < 6; kt++) {
                    const int k0 = kt * 16 + tg * 2;
                    const int kg = c * CHK + kt * 16 + tg * 2;
                    uint32_t af[2][4];
#pragma unroll
                    for (int mf = 0; mf < 2; mf++) {
                        const int r = wm * 32 + mf * 16 + gid;
                        af[mf][0] = *(const uint32_t*)(&A[r * APAD + k0]);
                        af[mf][1] = *(const uint32_t*)(&A[(r + 8) * APAD + k0]);
                        af[mf][2] = *(const uint32_t*)(&A[r * APAD + k0 + 8]);
                        af[mf][3] = *(const uint32_t*)(&A[(r + 8) * APAD + k0 + 8]);
                    }
                    uint32_t bfr[5][2];
#pragma unroll
                    for (int nf = 0; nf < 5; nf++) {
                        const int cc = wn * 40 + nf * 8 + gid;
                        bfr[nf][0] = *(const uint32_t*)(&Wsm[cc * WPAD + kg]);
                        bfr[nf][1] = *(const uint32_t*)(&Wsm[cc * WPAD + kg + 8]);
                    }
#pragma unroll
                    for (int mf = 0; mf < 2; mf++)
#pragma unroll
                        for (int nf = 0; nf < 5; nf++)
                            mma_bf16(acc[mf][nf], af[mf], bfr[nf]);
                }
            }

#pragma unroll
            for (int mf = 0; mf < 2; mf++)
#pragma unroll
                for (int nf = 0; nf < 5; nf++) {
                    const int row = mbase + wm * 32 + mf * 16 + gid;
                    const int col = nbase + wn * 40 + nf * 8 + tg * 2;
                    *(float2*)(&g_tmp[(size_t)row * TMPN + col]) =
                        make_float2(acc[mf][nf][0], acc[mf][nf][1]);
                    *(float2*)(&g_tmp[(size_t)(row + 8) * TMPN + col]) =
                        make_float2(acc[mf][nf][2], acc[mf][nf][3]);
                }
        }

        // prefetch step-local independent data (retires during barrier spin)
        float qv[8];
#pragma unroll
        for (int r = 0; r < 8; r++)
            qv[r] = q1e[((size_t)(b0 + r) * TSTEPS + t) * 256 + tid];
        float epsv = noise[((size_t)t * BSZ + (b0 + (tid >> 5))) * SDIM + (tid & 31)];
        float actv = 0.f;
        if (tid < 8 * ACTD)
            actv = act[((size_t)(b0 + (tid >> 3)) * TSTEPS + t) * ACTD + (tid & 7)];

        group_sync(bs);

        // ======== phase S ========
        // stage 1: biases + ELU
#pragma unroll
        for (int r = 0; r < 8; r++) {
            int b = b0 + r;
            const float* trow = g_tmp + (size_t)b * TMPN;
            float p = trow[tid] + bp1[tid];
            PQ[(0 * 8 + r) * 256 + tid] = p > 0.f ? p : expm1f(p);
            float q = trow[256 + tid] + qv[r];
            PQ[(1 * 8 + r) * 256 + tid] = q > 0.f ? q : expm1f(q);
        }
        __syncthreads();

        // stage 2: prior/posterior stats
        {
            int j = tid & 127;
            int rbase = tid >> 7;
            bool isq = (j >= 64);
            int jj = isq ? j - 64 : j;
            const float* wrow = (isq ? Wq2 : Wp2) + jj * 256;
            float bb = (isq ? bq2 : bp2)[jj];
            const float* base = PQ + (isq ? 8 * 256 : 0);

            float accm[4] = {0.f, 0.f, 0.f, 0.f};
            for (int k = 0; k < 256; k += 4) {
                float4 w = *(const float4*)(wrow + k);
#pragma unroll
                for (int m = 0; m < 4; m++) {
                    int r = rbase + 2 * m;
                    float4 s = *(const float4*)(base + r * 256 + k);
                    accm[m] += s.x * w.x + s.y * w.y + s.z * w.z + s.w * w.w;
                }
            }
#pragma unroll
            for (int m = 0; m < 4; m++) ST[(rbase + 2 * m) * 128 + j] = accm[m] + bb;
        }
        __syncthreads();

        // stage 3: z = qm + qs*eps ; stage act
        {
            int r = tid >> 5, s = tid & 31;
            float qm = ST[r * 128 + 64 + s];
            float ql = fminf(fmaxf(ST[r * 128 + 96 + s], -7.f), 5.f);
            float qs = expf(ql);
            ZA[r * 40 + s] = qm + qs * epsv;
        }
        if (tid < 8 * ACTD) {
            int r = tid >> 3, j = tid & 7;
            ZA[r * 40 + 32 + j] = actv;
        }
        __syncthreads();

        // stage 4: GRU gates + h update (h in registers) + write h_old + split h_new
#pragma unroll 1
        for (int r = 0; r < 8; r++) {
            int d = tid;
            int b = b0 + r;
            float gi[3];
#pragma unroll
            for (int g = 0; g < 3; g++) {
                const float* w = Wih + (size_t)(g * 256 + d) * 40;
                float a = 0.f;
#pragma unroll
                for (int k4 = 0; k4 < 10; k4++) {
                    float4 wv = *(const float4*)(w + 4 * k4);
                    float4 sv = *(const float4*)(&ZA[r * 40 + 4 * k4]);
                    a += sv.x * wv.x + sv.y * wv.y + sv.z * wv.z + sv.w * wv.w;
                }
                gi[g] = a + bih[g * 256 + d];
            }
            const float* trow = g_tmp + (size_t)b * TMPN + 512;
            float ghr = trow[d]        + bhh[d];
            float ghu = trow[256 + d]  + bhh[256 + d];
            float ghn = trow[512 + d]  + bhh[512 + d];
            float rg = sigmf(gi[0] + ghr);
            float u  = sigmf(gi[1] + ghu);
            float nn = tanhf(gi[2] + rg * ghn);
            float hold = hreg[r];
            float hnew = (1.f - u) * nn + u * hold;
            out[((size_t)b * TSTEPS + t) * OUTW + d] = hold;
            hreg[r] = hnew;
            __nv_bfloat16 hi, lo; split_bf16(hnew, hi, lo);
            __nv_bfloat16* arow = g_Ah + (size_t)b * 768;
            arow[d] = hi; arow[256 + d] = hi; arow[512 + d] = lo;
        }

        // stage 5: write z, pm, ps, qm, qs
        for (int i = tid; i < 8 * 160; i += 256) {
            int r = i / 160, c = i - r * 160;
            int b = b0 + r;
            float v;
            if (c < 32) {
                v = ZA[r * 40 + c];
            } else {
                v = ST[r * 128 + c - 32];
                if ((c >= 64 && c < 96) || c >= 128) {
                    v = expf(fminf(fmaxf(v, -7.f), 5.f));
                }
            }
            out[((size_t)b * TSTEPS + t) * OUTW + 256 + c] = v;
        }
        group_sync(bs);
    }
}

// ---------------- host launch ----------------
extern "C" void kernel_launch(void* const* d_in, const int* in_sizes, int n_in,
                              void* d_out, int out_size)
{
    (void)in_sizes; (void)n_in; (void)out_size;
    const float* obs  = (const float*)d_in[0];
    const float* actp = (const float*)d_in[1];
    const float* noi  = (const float*)d_in[2];
    const float* We1  = (const float*)d_in[3];
    const float* be1  = (const float*)d_in[4];
    const float* We2  = (const float*)d_in[5];
    const float* be2  = (const float*)d_in[6];
    const float* Wih  = (const float*)d_in[7];
    const float* Whh  = (const float*)d_in[8];
    const float* bih  = (const float*)d_in[9];
    const float* bhh  = (const float*)d_in[10];
    const float* Wp1  = (const float*)d_in[11];
    const float* bp1  = (const float*)d_in[12];
    const float* Wp2  = (const float*)d_in[13];
    const float* bp2  = (const float*)d_in[14];
    const float* Wq1  = (const float*)d_in[15];
    const float* bq1  = (const float*)d_in[16];
    const float* Wq2  = (const float*)d_in[17];
    const float* bq2  = (const float*)d_in[18];
    float* out = (float*)d_out;

    float* p_q1e;
    __nv_bfloat16* p_Ah;
    cudaGetSymbolAddress((void**)&p_q1e, g_q1e);
    cudaGetSymbolAddress((void**)&p_Ah,  g_Ah);

    cudaFuncSetAttribute(mlp_kernel,
                         cudaFuncAttributeMaxDynamicSharedMemorySize, MS_TOTAL);
    cudaFuncSetAttribute(scan_kernel,
                         cudaFuncAttributeMaxDynamicSharedMemorySize, SM_TOTAL);

    cudaMemsetAsync(p_Ah, 0, sizeof(__nv_bfloat16) * BSZ * 768, 0);

    pack_all_kernel<<<(PKTOT + 255) / 256, 256>>>(Wp1, Wq1, Whh, We1, We2);

    mlp_kernel<<<NROWS / MRM, 256, MS_TOTAL>>>(obs, be1, be2, bq1, p_q1e);

    scan_kernel<<<NBLK, 256, SM_TOTAL>>>(p_q1e, noi, actp,
                                         Wp2, bp2, Wq2, bq2, bp1,
                                         Wih, bih, bhh, out);
}

// round 15
// speedup vs baseline: 1.0991x; 1.0991x over previous
#include <cuda_runtime.h>
#include <cuda_bf16.h>
#include <cstdint>

// Problem constants
#define OBS 64
#define ACTD 8
#define DDIM 256
#define SDIM 32
#define HDIM 256
#define BSZ 1024
#define TSTEPS 128
#define TMPN 1280          // D(prior) + D(post-h) + 3D(gru)
#define OUTW 416           // D + 5*S
#define NROWS (BSZ*TSTEPS) // 131072

// ---------------- device scratch ----------------
__device__ float g_h[BSZ * DDIM];                       // fp32 h state
__device__ float g_tmp[BSZ * TMPN];                     // per-step GEMM out
__device__ float g_q1e[(size_t)NROWS * HDIM];           // fp32 posterior emb-side preact
__device__ __nv_bfloat16 g_Ah[BSZ * 768];               // h split [hi|hi|lo] (scan)
__device__ __nv_bfloat16 g_Wcat[TMPN * 768];            // [Wp1;Wq1h;Whh] split (scan)
// MLP weights, hi/lo pairs
__device__ __nv_bfloat16 g_W1hi[256 * 64],  g_W1lo[256 * 64];
__device__ __nv_bfloat16 g_W2hi[256 * 256], g_W2lo[256 * 256];
__device__ __nv_bfloat16 g_W3hi[256 * 256], g_W3lo[256 * 256];

// group barrier state: 8 strips, each on its own 128B line
__device__ unsigned g_grp_cnt[8 * 32];
__device__ volatile unsigned g_grp_gen[8 * 32];

// ---------------- fast transcendentals (hardware EX2-based) ----------------
__device__ __forceinline__ float elu1(float x) {
    return x > 0.f ? x : (__expf(x) - 1.f);
}
__device__ __forceinline__ float sigmf(float x) {
    return __fdividef(1.f, 1.f + __expf(-x));
}
__device__ __forceinline__ float tanhfast(float x) {
    return 1.f - __fdividef(2.f, __expf(2.f * x) + 1.f);
}
__device__ __forceinline__ float expclip(float x) {
    return __expf(fminf(fmaxf(x, -7.f), 5.f));
}

// ---------------- split helpers ----------------
__device__ __forceinline__ void split_bf16(float x, __nv_bfloat16& hi, __nv_bfloat16& lo) {
    hi = __float2bfloat16_rn(x);
    lo = __float2bfloat16_rn(x - __bfloat162float(hi));
}

// ---------------- single fused pack kernel ----------------
#define PK0 65536
#define PK1 65536
#define PK2 196608
#define PK3 16384
#define PK4 65536
#define PK5 65536
#define PKTOT (PK0+PK1+PK2+PK3+PK4+PK5)

__global__ void pack_all_kernel(const float* __restrict__ Wp1,
                                const float* __restrict__ Wq1,
                                const float* __restrict__ Whh,
                                const float* __restrict__ We1,
                                const float* __restrict__ We2)
{
    int idx = blockIdx.x * blockDim.x + threadIdx.x;
    if (idx >= PKTOT) return;
    if (idx < PK0 + PK1 + PK2) {
        int j, k;
        float w;
        int rbase;
        if (idx < PK0) {
            j = idx >> 8; k = idx & 255; rbase = 0;
            w = Wp1[j * 256 + k];
        } else if (idx < PK0 + PK1) {
            int i2 = idx - PK0;
            j = i2 >> 8; k = i2 & 255; rbase = 256;
            w = Wq1[(size_t)j * 512 + k];
        } else {
            int i2 = idx - PK0 - PK1;
            j = i2 >> 8; k = i2 & 255; rbase = 512;
            w = Whh[(size_t)j * 256 + k];
        }
        __nv_bfloat16 hi, lo; split_bf16(w, hi, lo);
        __nv_bfloat16* d = g_Wcat + (size_t)(rbase + j) * 768;
        d[k] = hi; d[256 + k] = lo; d[512 + k] = hi;
    } else {
        int i2 = idx - (PK0 + PK1 + PK2);
        float w;
        __nv_bfloat16 *dhi, *dlo;
        int off;
        if (i2 < PK3) {
            int j = i2 >> 6, k = i2 & 63;
            w = We1[j * 64 + k]; dhi = g_W1hi; dlo = g_W1lo; off = i2;
        } else if (i2 < PK3 + PK4) {
            int i3 = i2 - PK3;
            int j = i3 >> 8, k = i3 & 255;
            w = We2[j * 256 + k]; dhi = g_W2hi; dlo = g_W2lo; off = i3;
        } else {
            int i3 = i2 - PK3 - PK4;
            int j = i3 >> 8, k = i3 & 255;
            w = Wq1[(size_t)j * 512 + 256 + k]; dhi = g_W3hi; dlo = g_W3lo; off = i3;
        }
        __nv_bfloat16 hi, lo; split_bf16(w, hi, lo);
        dhi[off] = hi; dlo[off] = lo;
    }
}

// dummy kernel: shifts scan_kernel into the ncu -s 5 -c 1 capture slot
__global__ void dummy_kernel() {}

// ---------------- mma helpers ----------------
__device__ __forceinline__ void mma_bf16(float* c, const uint32_t* a, const uint32_t* b) {
    asm volatile(
        "mma.sync.aligned.m16n8k16.row.col.f32.bf16.bf16.f32 "
        "{%0,%1,%2,%3}, {%4,%5,%6,%7}, {%8,%9}, {%0,%1,%2,%3};\n"
        : "+f"(c[0]), "+f"(c[1]), "+f"(c[2]), "+f"(c[3])
        : "r"(a[0]), "r"(a[1]), "r"(a[2]), "r"(a[3]), "r"(b[0]), "r"(b[1]));
}

__device__ __forceinline__ uint32_t smem_u32(const void* p) {
    return (uint32_t)__cvta_generic_to_shared(p);
}
__device__ __forceinline__ void cp16(void* dst, const void* src) {
    asm volatile("cp.async.cg.shared.global [%0], [%1], 16;\n"
                 :: "r"(smem_u32(dst)), "l"(src));
}
__device__ __forceinline__ void cp_commit() { asm volatile("cp.async.commit_group;\n"); }
template <int N>
__device__ __forceinline__ void cp_wait() { asm volatile("cp.async.wait_group %0;\n"::"n"(N)); }

// ================= fused precompute MLP kernel =================
#define MRM 64
#define SA 264
#define SW 72
#define MS_AH 0
#define MS_AL (MRM * SA * 2)
#define MS_W  (2 * MRM * SA * 2)
#define MS_WPART (256 * SW * 2)
#define MS_TOTAL (MS_W + 4 * MS_WPART)

__device__ __forceinline__ void mma_tiles3(
    const __nv_bfloat16* AH, const __nv_bfloat16* AL,
    const __nv_bfloat16* WH, const __nv_bfloat16* WL,
    int kbase, int wm, int wn, int gid, int tg,
    float (*acc)[8][4])
{
#pragma unroll
    for (int kt = 0; kt < 4; kt++) {
        const int ka = kbase + kt * 16 + tg * 2;
        const int kw = kt * 16 + tg * 2;
        uint32_t ah[2][4], al[2][4];
#pragma unroll
        for (int mf = 0; mf < 2; mf++) {
            const int R = wm * 32 + mf * 16 + gid;
            ah[mf][0] = *(const uint32_t*)(&AH[R * SA + ka]);
            ah[mf][1] = *(const uint32_t*)(&AH[(R + 8) * SA + ka]);
            ah[mf][2] = *(const uint32_t*)(&AH[R * SA + ka + 8]);
            ah[mf][3] = *(const uint32_t*)(&AH[(R + 8) * SA + ka + 8]);
            al[mf][0] = *(const uint32_t*)(&AL[R * SA + ka]);
            al[mf][1] = *(const uint32_t*)(&AL[(R + 8) * SA + ka]);
            al[mf][2] = *(const uint32_t*)(&AL[R * SA + ka + 8]);
            al[mf][3] = *(const uint32_t*)(&AL[(R + 8) * SA + ka + 8]);
        }
#pragma unroll
        for (int nf = 0; nf < 8; nf++) {
            const int C = wn * 64 + nf * 8 + gid;
            uint32_t bh[2], bl[2];
            bh[0] = *(const uint32_t*)(&WH[C * SW + kw]);
            bh[1] = *(const uint32_t*)(&WH[C * SW + kw + 8]);
            bl[0] = *(const uint32_t*)(&WL[C * SW + kw]);
            bl[1] = *(const uint32_t*)(&WL[C * SW + kw + 8]);
#pragma unroll
            for (int mf = 0; mf < 2; mf++) {
                mma_bf16(acc[mf][nf], ah[mf], bh);
                mma_bf16(acc[mf][nf], ah[mf], bl);
                mma_bf16(acc[mf][nf], al[mf], bh);
            }
        }
    }
}

__device__ __forceinline__ void issue_wchunk(
    char* sm, int stage, int tid,
    const __nv_bfloat16* Ghi, const __nv_bfloat16* Glo, int gld, int kofs)
{
    __nv_bfloat16* WH = (__nv_bfloat16*)(sm + MS_W + (stage * 2 + 0) * MS_WPART);
    __nv_bfloat16* WL = (__nv_bfloat16*)(sm + MS_W + (stage * 2 + 1) * MS_WPART);
#pragma unroll
    for (int j = 0; j < 8; j++) {
        int idx = tid + j * 256;
        int n = idx >> 3, kk = (idx & 7) * 8;
        cp16(&WH[n * SW + kk], &Ghi[(size_t)n * gld + kofs + kk]);
        cp16(&WL[n * SW + kk], &Glo[(size_t)n * gld + kofs + kk]);
    }
    cp_commit();
}

__global__ __launch_bounds__(256, 1) void mlp_kernel(
    const float* __restrict__ obs,
    const float* __restrict__ be1,
    const float* __restrict__ be2,
    const float* __restrict__ bq1,
    float* __restrict__ q1e)
{
    extern __shared__ char sm[];
    __nv_bfloat16* AH = (__nv_bfloat16*)(sm + MS_AH);
    __nv_bfloat16* AL = (__nv_bfloat16*)(sm + MS_AL);

    const int tid = threadIdx.x;
    const int lane = tid & 31;
    const int warp = tid >> 5;
    const int gid = lane >> 2;
    const int tg = lane & 3;
    const int wm = warp & 1;
    const int wn = warp >> 1;
    const size_t row0 = (size_t)blockIdx.x * MRM;

    float acc[2][8][4];

    for (int i = tid; i < MRM * OBS; i += 256) {
        int r = i >> 6, c = i & 63;
        float v = obs[(row0 + r) * OBS + c];
        __nv_bfloat16 hi, lo; split_bf16(v, hi, lo);
        AH[r * SA + c] = hi; AL[r * SA + c] = lo;
    }
    {
        __nv_bfloat16* WH = (__nv_bfloat16*)(sm + MS_W + 0 * MS_WPART);
        __nv_bfloat16* WL = (__nv_bfloat16*)(sm + MS_W + 1 * MS_WPART);
#pragma unroll
        for (int j = 0; j < 8; j++) {
            int idx = tid + j * 256;
            int n = idx >> 3, kk = (idx & 7) * 8;
            cp16(&WH[n * SW + kk], &g_W1hi[n * 64 + kk]);
            cp16(&WL[n * SW + kk], &g_W1lo[n * 64 + kk]);
        }
        cp_commit();
    }
    cp_wait<0>();
    __syncthreads();

#pragma unroll
    for (int mf = 0; mf < 2; mf++)
#pragma unroll
        for (int nf = 0; nf < 8; nf++)
#pragma unroll
            for (int q = 0; q < 4; q++) acc[mf][nf][q] = 0.f;
    mma_tiles3(AH, AL,
               (__nv_bfloat16*)(sm + MS_W + 0 * MS_WPART),
               (__nv_bfloat16*)(sm + MS_W + 1 * MS_WPART),
               0, wm, wn, gid, tg, acc);
    __syncthreads();
#pragma unroll
    for (int mf = 0; mf < 2; mf++)
#pragma unroll
        for (int nf = 0; nf < 8; nf++) {
            const int R = wm * 32 + mf * 16 + gid;
            const int C = wn * 64 + nf * 8 + tg * 2;
            float b0 = be1[C], b1 = be1[C + 1];
            float v0 = elu1(acc[mf][nf][0] + b0), v1 = elu1(acc[mf][nf][1] + b1);
            float v2 = elu1(acc[mf][nf][2] + b0), v3 = elu1(acc[mf][nf][3] + b1);
            __nv_bfloat16 h0, l0, h1, l1, h2, l2, h3, l3;
            split_bf16(v0, h0, l0); split_bf16(v1, h1, l1);
            split_bf16(v2, h2, l2); split_bf16(v3, h3, l3);
            *(__nv_bfloat162*)(&AH[R * SA + C])       = __nv_bfloat162(h0, h1);
            *(__nv_bfloat162*)(&AL[R * SA + C])       = __nv_bfloat162(l0, l1);
            *(__nv_bfloat162*)(&AH[(R + 8) * SA + C]) = __nv_bfloat162(h2, h3);
            *(__nv_bfloat162*)(&AL[(R + 8) * SA + C]) = __nv_bfloat162(l2, l3);
        }
    __syncthreads();

    for (int layer = 0; layer < 2; layer++) {
        const __nv_bfloat16* Ghi = layer == 0 ? g_W2hi : g_W3hi;
        const __nv_bfloat16* Glo = layer == 0 ? g_W2lo : g_W3lo;
        const float* bias = layer == 0 ? be2 : bq1;

#pragma unroll
        for (int mf = 0; mf < 2; mf++)
#pragma unroll
            for (int nf = 0; nf < 8; nf++)
#pragma unroll
                for (int q = 0; q < 4; q++) acc[mf][nf][q] = 0.f;

        issue_wchunk(sm, 0, tid, Ghi, Glo, 256, 0);
        for (int c = 0; c < 4; c++) {
            if (c + 1 < 4) {
                issue_wchunk(sm, (c + 1) & 1, tid, Ghi, Glo, 256, (c + 1) * 64);
                cp_wait<1>();
            } else {
                cp_wait<0>();
            }
            __syncthreads();
            mma_tiles3(AH, AL,
                       (__nv_bfloat16*)(sm + MS_W + ((c & 1) * 2 + 0) * MS_WPART),
                       (__nv_bfloat16*)(sm + MS_W + ((c & 1) * 2 + 1) * MS_WPART),
                       c * 64, wm, wn, gid, tg, acc);
            __syncthreads();
        }

        if (layer == 0) {
#pragma unroll
            for (int mf = 0; mf < 2; mf++)
#pragma unroll
                for (int nf = 0; nf < 8; nf++) {
                    const int R = wm * 32 + mf * 16 + gid;
                    const int C = wn * 64 + nf * 8 + tg * 2;
                    float b0 = bias[C], b1 = bias[C + 1];
                    float v0 = elu1(acc[mf][nf][0] + b0), v1 = elu1(acc[mf][nf][1] + b1);
                    float v2 = elu1(acc[mf][nf][2] + b0), v3 = elu1(acc[mf][nf][3] + b1);
                    __nv_bfloat16 h0, l0, h1, l1, h2, l2, h3, l3;
                    split_bf16(v0, h0, l0); split_bf16(v1, h1, l1);
                    split_bf16(v2, h2, l2); split_bf16(v3, h3, l3);
                    *(__nv_bfloat162*)(&AH[R * SA + C])       = __nv_bfloat162(h0, h1);
                    *(__nv_bfloat162*)(&AL[R * SA + C])       = __nv_bfloat162(l0, l1);
                    *(__nv_bfloat162*)(&AH[(R + 8) * SA + C]) = __nv_bfloat162(h2, h3);
                    *(__nv_bfloat162*)(&AL[(R + 8) * SA + C]) = __nv_bfloat162(l2, l3);
                }
            __syncthreads();
        } else {
#pragma unroll
            for (int mf = 0; mf < 2; mf++)
#pragma unroll
                for (int nf = 0; nf < 8; nf++) {
                    const int R = wm * 32 + mf * 16 + gid;
                    const int C = wn * 64 + nf * 8 + tg * 2;
                    float b0 = bias[C], b1 = bias[C + 1];
                    *(float2*)(&q1e[(row0 + R) * 256 + C]) =
                        make_float2(acc[mf][nf][0] + b0, acc[mf][nf][1] + b1);
                    *(float2*)(&q1e[(row0 + R + 8) * 256 + C]) =
                        make_float2(acc[mf][nf][2] + b0, acc[mf][nf][3] + b1);
                }
        }
    }
}

// ================= persistent scan kernel (R10 structure) =================
#define NBLK 128
#define WSLICE 80
#define WPAD 776
// phase-G A pipeline: chunks of 96 cols, double-buffered
#define CHK 96
#define NCHK 8           // 768 / 96
#define APAD 104         // A chunk row stride (bf16): 52 words, conflict-free
#define ACHUNK (128 * APAD)  // elements per buffer

#define SM_W    0
#define SM_AS   (WSLICE * WPAD * 2)                  // 124160
#define SM_PQ   (SM_AS + 2 * ACHUNK * 2)             // +53248 = 177408
#define SM_ST   (SM_PQ + 2 * 8 * 256 * 4)            // +16384 = 193792
#define SM_ZA   (SM_ST + 8 * 128 * 4)                // +4096  = 197888
#define SM_TOTAL (SM_ZA + 8 * 40 * 4)                // +1280  = 199168

// 16-block group barrier for strip s
__device__ __forceinline__ void group_sync(int s) {
    __syncthreads();
    if (threadIdx.x == 0) {
        __threadfence();
        unsigned* cnt = &g_grp_cnt[s * 32];
        volatile unsigned* gen = &g_grp_gen[s * 32];
        unsigned g = *gen;
        unsigned arrived = atomicAdd(cnt, 1u);
        if (arrived == 15u) {
            *cnt = 0u;
            __threadfence();
            *gen = g + 1u;
        } else {
            while (*gen == g) { }
        }
        __threadfence();
    }
    __syncthreads();
}

// issue cp.async load of one 128x96 A chunk into buffer buf
__device__ __forceinline__ void issue_achunk(char* smraw, int buf, int tid,
                                             int mbase, int kofs)
{
    __nv_bfloat16* dst = (__nv_bfloat16*)(smraw + SM_AS) + buf * ACHUNK;
#pragma unroll
    for (int j = 0; j < 6; j++) {
        int idx = j * 256 + tid;          // 0..1535
        int row = idx / 12, cc = idx % 12;
        cp16(&dst[row * APAD + cc * 8],
             &g_Ah[(size_t)(mbase + row) * 768 + kofs + cc * 8]);
    }
    cp_commit();
}

__global__ __launch_bounds__(256, 1) void scan_kernel(
    const float* __restrict__ q1e,
    const float* __restrict__ noise,
    const float* __restrict__ act,
    const float* __restrict__ Wp2, const float* __restrict__ bp2,
    const float* __restrict__ Wq2, const float* __restrict__ bq2,
    const float* __restrict__ bp1,
    const float* __restrict__ Wih, const float* __restrict__ bih,
    const float* __restrict__ bhh,
    float* __restrict__ out)
{
    extern __shared__ char smraw[];
    __nv_bfloat16* Wsm = (__nv_bfloat16*)(smraw + SM_W);
    float* PQ = (float*)(smraw + SM_PQ);
    float* ST = (float*)(smraw + SM_ST);
    float* ZA = (float*)(smraw + SM_ZA);

    const int tid = threadIdx.x;
    const int blk = blockIdx.x;
    const int lane = tid & 31;
    const int warp = tid >> 5;
    const int gid = lane >> 2;
    const int tg = lane & 3;
    const int wm = warp & 3;
    const int wn = warp >> 2;
    const int bs = blk >> 4;
    const int cs = blk & 15;
    const int mbase = bs * 128;
    const int nbase = cs * WSLICE;
    const int b0 = blk * 8;

    for (int i = tid; i < WSLICE * 768; i += 256) {
        int r = i / 768, k = i - r * 768;
        Wsm[r * WPAD + k] = g_Wcat[(size_t)(nbase + r) * 768 + k];
    }
    __syncthreads();

    for (int t = 0; t < TSTEPS; t++) {
        // ======== phase G: tmp = h_split @ Wslice^T (cp.async k-pipeline) ========
        {
            float acc[2][5][4];
#pragma unroll
            for (int i = 0; i < 2; i++)
#pragma unroll
                for (int j = 0; j < 5; j++)
#pragma unroll
                    for (int q = 0; q < 4; q++) acc[i][j][q] = 0.f;

            issue_achunk(smraw, 0, tid, mbase, 0);
            for (int c = 0; c < NCHK; c++) {
                if (c + 1 < NCHK) {
                    issue_achunk(smraw, (c + 1) & 1, tid, mbase, (c + 1) * CHK);
                    cp_wait<1>();
                } else {
                    cp_wait<0>();
                }
                __syncthreads();
                const __nv_bfloat16* A =
                    (const __nv_bfloat16*)(smraw + SM_AS) + (c & 1) * ACHUNK;
#pragma unroll
                for (int kt = 0; kt < 6; kt++) {
                    const int k0 = kt * 16 + tg * 2;
                    const int kg = c * CHK + kt * 16 + tg * 2;
                    uint32_t af[2][4];
#pragma unroll
                    for (int mf = 0; mf < 2; mf++) {
                        const int r = wm * 32 + mf * 16 + gid;
                        af[mf][0] = *(const uint32_t*)(&A[r * APAD + k0]);
                        af[mf][1] = *(const uint32_t*)(&A[(r + 8) * APAD + k0]);
                        af[mf][2] = *(const uint32_t*)(&A[r * APAD + k0 + 8]);
                        af[mf][3] = *(const uint32_t*)(&A[(r + 8) * APAD + k0 + 8]);
                    }
                    uint32_t bfr[5][2];
#pragma unroll
                    for (int nf = 0; nf < 5; nf++) {
                        const int cc = wn * 40 + nf * 8 + gid;
                        bfr[nf][0] = *(const uint32_t*)(&Wsm[cc * WPAD + kg]);
                        bfr[nf][1] = *(const uint32_t*)(&Wsm[cc * WPAD + kg + 8]);
                    }
#pragma unroll
                    for (int mf = 0; mf < 2; mf++)
#pragma unroll
                        for (int nf = 0; nf < 5; nf++)
                            mma_bf16(acc[mf][nf], af[mf], bfr[nf]);
                }
                __syncthreads();
            }

#pragma unroll
            for (int mf = 0; mf < 2; mf++)
#pragma unroll
                for (int nf = 0; nf < 5; nf++) {
                    const int row = mbase + wm * 32 + mf * 16 + gid;
                    const int col = nbase + wn * 40 + nf * 8 + tg * 2;
                    *(float2*)(&g_tmp[(size_t)row * TMPN + col]) =
                        make_float2(acc[mf][nf][0], acc[mf][nf][1]);
                    *(float2*)(&g_tmp[(size_t)(row + 8) * TMPN + col]) =
                        make_float2(acc[mf][nf][2], acc[mf][nf][3]);
                }
        }

        // prefetch step-local independent data (retires during barrier spin)
        float qv[8];
#pragma unroll
        for (int r = 0; r < 8; r++)
            qv[r] = q1e[((size_t)(b0 + r) * TSTEPS + t) * 256 + tid];
        float epsv = noise[((size_t)t * BSZ + (b0 + (tid >> 5))) * SDIM + (tid & 31)];
        float actv = 0.f;
        if (tid < 8 * ACTD)
            actv = act[((size_t)(b0 + (tid >> 3)) * TSTEPS + t) * ACTD + (tid & 7)];

        group_sync(bs);

        // ======== phase S ========
        // stage 1: biases + ELU
#pragma unroll
        for (int r = 0; r < 8; r++) {
            int b = b0 + r;
            const float* trow = g_tmp + (size_t)b * TMPN;
            PQ[(0 * 8 + r) * 256 + tid] = elu1(trow[tid] + bp1[tid]);
            PQ[(1 * 8 + r) * 256 + tid] = elu1(trow[256 + tid] + qv[r]);
        }
        __syncthreads();

        // stage 2: prior/posterior stats
        {
            int j = tid & 127;
            int rbase = tid >> 7;
            bool isq = (j >= 64);
            int jj = isq ? j - 64 : j;
            const float* wrow = (isq ? Wq2 : Wp2) + jj * 256;
            float bb = (isq ? bq2 : bp2)[jj];
            const float* base = PQ + (isq ? 8 * 256 : 0);

            float accm[4] = {0.f, 0.f, 0.f, 0.f};
            for (int k = 0; k < 256; k += 4) {
                float4 w = *(const float4*)(wrow + k);
#pragma unroll
                for (int m = 0; m < 4; m++) {
                    int r = rbase + 2 * m;
                    float4 s = *(const float4*)(base + r * 256 + k);
                    accm[m] += s.x * w.x + s.y * w.y + s.z * w.z + s.w * w.w;
                }
            }
#pragma unroll
            for (int m = 0; m < 4; m++) ST[(rbase + 2 * m) * 128 + j] = accm[m] + bb;
        }
        __syncthreads();

        // stage 3: z = qm + qs*eps ; stage act
        {
            int r = tid >> 5, s = tid & 31;
            float qm = ST[r * 128 + 64 + s];
            float qs = expclip(ST[r * 128 + 96 + s]);
            ZA[r * 40 + s] = qm + qs * epsv;
        }
        if (tid < 8 * ACTD) {
            int r = tid >> 3, j = tid & 7;
            ZA[r * 40 + 32 + j] = actv;
        }
        __syncthreads();

        // stage 4: GRU gates + h update + write h_old + split h_new
#pragma unroll 1
        for (int r = 0; r < 8; r++) {
            int d = tid;
            int b = b0 + r;
            float gi[3];
#pragma unroll
            for (int g = 0; g < 3; g++) {
                const float* w = Wih + (size_t)(g * 256 + d) * 40;
                float a = 0.f;
#pragma unroll
                for (int k4 = 0; k4 < 10; k4++) {
                    float4 wv = *(const float4*)(w + 4 * k4);
                    float4 sv = *(const float4*)(&ZA[r * 40 + 4 * k4]);
                    a += sv.x * wv.x + sv.y * wv.y + sv.z * wv.z + sv.w * wv.w;
                }
                gi[g] = a + bih[g * 256 + d];
            }
            const float* trow = g_tmp + (size_t)b * TMPN + 512;
            float ghr = trow[d]        + bhh[d];
            float ghu = trow[256 + d]  + bhh[256 + d];
            float ghn = trow[512 + d]  + bhh[512 + d];
            float rg = sigmf(gi[0] + ghr);
            float u  = sigmf(gi[1] + ghu);
            float nn = tanhfast(gi[2] + rg * ghn);
            float hold = g_h[(size_t)b * DDIM + d];
            float hnew = (1.f - u) * nn + u * hold;
            out[((size_t)b * TSTEPS + t) * OUTW + d] = hold;
            g_h[(size_t)b * DDIM + d] = hnew;
            __nv_bfloat16 hi, lo; split_bf16(hnew, hi, lo);
            __nv_bfloat16* arow = g_Ah + (size_t)b * 768;
            arow[d] = hi; arow[256 + d] = hi; arow[512 + d] = lo;
        }

        // stage 5: write z, pm, ps, qm, qs
        for (int i = tid; i < 8 * 160; i += 256) {
            int r = i / 160, c = i - r * 160;
            int b = b0 + r;
            float v;
            if (c < 32) {
                v = ZA[r * 40 + c];
            } else {
                v = ST[r * 128 + c - 32];
                if ((c >= 64 && c < 96) || c >= 128) {
                    v = expclip(v);
                }
            }
            out[((size_t)b * TSTEPS + t) * OUTW + 256 + c] = v;
        }
        group_sync(bs);
    }
}

// ---------------- host launch ----------------
extern "C" void kernel_launch(void* const* d_in, const int* in_sizes, int n_in,
                              void* d_out, int out_size)
{
    (void)in_sizes; (void)n_in; (void)out_size;
    const float* obs  = (const float*)d_in[0];
    const float* actp = (const float*)d_in[1];
    const float* noi  = (const float*)d_in[2];
    const float* We1  = (const float*)d_in[3];
    const float* be1  = (const float*)d_in[4];
    const float* We2  = (const float*)d_in[5];
    const float* be2  = (const float*)d_in[6];
    const float* Wih  = (const float*)d_in[7];
    const float* Whh  = (const float*)d_in[8];
    const float* bih  = (const float*)d_in[9];
    const float* bhh  = (const float*)d_in[10];
    const float* Wp1  = (const float*)d_in[11];
    const float* bp1  = (const float*)d_in[12];
    const float* Wp2  = (const float*)d_in[13];
    const float* bp2  = (const float*)d_in[14];
    const float* Wq1  = (const float*)d_in[15];
    const float* bq1  = (const float*)d_in[16];
    const float* Wq2  = (const float*)d_in[17];
    const float* bq2  = (const float*)d_in[18];
    float* out = (float*)d_out;

    float *p_h, *p_q1e;
    __nv_bfloat16* p_Ah;
    cudaGetSymbolAddress((void**)&p_h,   g_h);
    cudaGetSymbolAddress((void**)&p_q1e, g_q1e);
    cudaGetSymbolAddress((void**)&p_Ah,  g_Ah);

    cudaFuncSetAttribute(mlp_kernel,
                         cudaFuncAttributeMaxDynamicSharedMemorySize, MS_TOTAL);
    cudaFuncSetAttribute(scan_kernel,
                         cudaFuncAttributeMaxDynamicSharedMemorySize, SM_TOTAL);

    // launches 1-5: memset, memset, pack, mlp, dummy  -> launch 6 = scan (ncu -s 5 -c 1)
    cudaMemsetAsync(p_h, 0, sizeof(float) * BSZ * DDIM, 0);
    cudaMemsetAsync(p_Ah, 0, sizeof(__nv_bfloat16) * BSZ * 768, 0);

    pack_all_kernel<<<(PKTOT + 255) / 256, 256>>>(Wp1, Wq1, Whh, We1, We2);

    mlp_kernel<<<NROWS / MRM, 256, MS_TOTAL>>>(obs, be1, be2, bq1, p_q1e);

    dummy_kernel<<<1, 32>>>();

    scan_kernel<<<NBLK, 256, SM_TOTAL>>>(p_q1e, noi, actp,
                                         Wp2, bp2, Wq2, bq2, bp1,
                                         Wih, bih, bhh, out);
}

// round 16
// speedup vs baseline: 1.3385x; 1.2178x over previous
#include <cuda_runtime.h>
#include <cuda_bf16.h>
#include <cstdint>

// Problem constants
#define OBS 64
#define ACTD 8
#define DDIM 256
#define SDIM 32
#define HDIM 256
#define BSZ 1024
#define TSTEPS 128
#define TMPN 1280          // D(prior) + D(post-h) + 3D(gru)
#define OUTW 416           // D + 5*S
#define NROWS (BSZ*TSTEPS) // 131072

// ---------------- device scratch ----------------
__device__ float g_h[BSZ * DDIM];                       // fp32 h state
__device__ float g_tmp[BSZ * TMPN];                     // per-step GEMM out
__device__ float g_q1e[(size_t)NROWS * HDIM];           // fp32 posterior emb-side preact
__device__ __nv_bfloat16 g_Ah[BSZ * 768];               // h split [hi|hi|lo] (scan)
__device__ __nv_bfloat16 g_Wcat[TMPN * 768];            // [Wp1;Wq1h;Whh] split (scan)
// coalesced k-major weight packs for phase S
__device__ float4 g_WihP[10 * 768];                     // [k4][g*256+d] = Wih[g*256+d][4k4..+3]
__device__ float4 g_W2P[64 * 128];                      // [k4][j] = (j<64?Wp2[j]:Wq2[j-64])[4k4..+3]
// MLP weights, hi/lo pairs
__device__ __nv_bfloat16 g_W1hi[256 * 64],  g_W1lo[256 * 64];
__device__ __nv_bfloat16 g_W2hi[256 * 256], g_W2lo[256 * 256];
__device__ __nv_bfloat16 g_W3hi[256 * 256], g_W3lo[256 * 256];

// group barrier state: 8 strips, each on its own 128B line
__device__ unsigned g_grp_cnt[8 * 32];
__device__ volatile unsigned g_grp_gen[8 * 32];

// ---------------- fast transcendentals ----------------
__device__ __forceinline__ float elu1(float x) {
    return x > 0.f ? x : (__expf(x) - 1.f);
}
__device__ __forceinline__ float sigmf(float x) {
    return __fdividef(1.f, 1.f + __expf(-x));
}
__device__ __forceinline__ float tanhfast(float x) {
    return 1.f - __fdividef(2.f, __expf(2.f * x) + 1.f);
}
__device__ __forceinline__ float expclip(float x) {
    return __expf(fminf(fmaxf(x, -7.f), 5.f));
}

// ---------------- split helpers ----------------
__device__ __forceinline__ void split_bf16(float x, __nv_bfloat16& hi, __nv_bfloat16& lo) {
    hi = __float2bfloat16_rn(x);
    lo = __float2bfloat16_rn(x - __bfloat162float(hi));
}

// ---------------- pack kernels ----------------
#define PK0 65536
#define PK1 65536
#define PK2 196608
#define PK3 16384
#define PK4 65536
#define PK5 65536
#define PKTOT (PK0+PK1+PK2+PK3+PK4+PK5)

__global__ void pack_all_kernel(const float* __restrict__ Wp1,
                                const float* __restrict__ Wq1,
                                const float* __restrict__ Whh,
                                const float* __restrict__ We1,
                                const float* __restrict__ We2)
{
    int idx = blockIdx.x * blockDim.x + threadIdx.x;
    if (idx >= PKTOT) return;
    if (idx < PK0 + PK1 + PK2) {
        int j, k;
        float w;
        int rbase;
        if (idx < PK0) {
            j = idx >> 8; k = idx & 255; rbase = 0;
            w = Wp1[j * 256 + k];
        } else if (idx < PK0 + PK1) {
            int i2 = idx - PK0;
            j = i2 >> 8; k = i2 & 255; rbase = 256;
            w = Wq1[(size_t)j * 512 + k];
        } else {
            int i2 = idx - PK0 - PK1;
            j = i2 >> 8; k = i2 & 255; rbase = 512;
            w = Whh[(size_t)j * 256 + k];
        }
        __nv_bfloat16 hi, lo; split_bf16(w, hi, lo);
        __nv_bfloat16* d = g_Wcat + (size_t)(rbase + j) * 768;
        d[k] = hi; d[256 + k] = lo; d[512 + k] = hi;
    } else {
        int i2 = idx - (PK0 + PK1 + PK2);
        float w;
        __nv_bfloat16 *dhi, *dlo;
        int off;
        if (i2 < PK3) {
            int j = i2 >> 6, k = i2 & 63;
            w = We1[j * 64 + k]; dhi = g_W1hi; dlo = g_W1lo; off = i2;
        } else if (i2 < PK3 + PK4) {
            int i3 = i2 - PK3;
            int j = i3 >> 8, k = i3 & 255;
            w = We2[j * 256 + k]; dhi = g_W2hi; dlo = g_W2lo; off = i3;
        } else {
            int i3 = i2 - PK3 - PK4;
            int j = i3 >> 8, k = i3 & 255;
            w = Wq1[(size_t)j * 512 + 256 + k]; dhi = g_W3hi; dlo = g_W3lo; off = i3;
        }
        __nv_bfloat16 hi, lo; split_bf16(w, hi, lo);
        dhi[off] = hi; dlo[off] = lo;
    }
}

// pack Wih / Wp2 / Wq2 into k-major coalesced float4 layout
#define PW_IH (10 * 768)
#define PW_2  (64 * 128)
__global__ void packW_kernel(const float* __restrict__ Wih,
                             const float* __restrict__ Wp2,
                             const float* __restrict__ Wq2)
{
    int idx = blockIdx.x * blockDim.x + threadIdx.x;
    if (idx < PW_IH) {
        int k4 = idx / 768, d3 = idx - k4 * 768;
        const float* s = Wih + (size_t)d3 * 40 + 4 * k4;
        g_WihP[idx] = make_float4(s[0], s[1], s[2], s[3]);
    } else if (idx < PW_IH + PW_2) {
        int i2 = idx - PW_IH;
        int k4 = i2 >> 7, j = i2 & 127;
        const float* s = (j < 64 ? Wp2 + j * 256 : Wq2 + (j - 64) * 256) + 4 * k4;
        g_W2P[i2] = make_float4(s[0], s[1], s[2], s[3]);
    }
}

// ---------------- mma helpers ----------------
__device__ __forceinline__ void mma_bf16(float* c, const uint32_t* a, const uint32_t* b) {
    asm volatile(
        "mma.sync.aligned.m16n8k16.row.col.f32.bf16.bf16.f32 "
        "{%0,%1,%2,%3}, {%4,%5,%6,%7}, {%8,%9}, {%0,%1,%2,%3};\n"
        : "+f"(c[0]), "+f"(c[1]), "+f"(c[2]), "+f"(c[3])
        : "r"(a[0]), "r"(a[1]), "r"(a[2]), "r"(a[3]), "r"(b[0]), "r"(b[1]));
}

__device__ __forceinline__ uint32_t smem_u32(const void* p) {
    return (uint32_t)__cvta_generic_to_shared(p);
}
__device__ __forceinline__ void cp16(void* dst, const void* src) {
    asm volatile("cp.async.cg.shared.global [%0], [%1], 16;\n"
                 :: "r"(smem_u32(dst)), "l"(src));
}
__device__ __forceinline__ void cp_commit() { asm volatile("cp.async.commit_group;\n"); }
template <int N>
__device__ __forceinline__ void cp_wait() { asm volatile("cp.async.wait_group %0;\n"::"n"(N)); }

// ================= fused precompute MLP kernel (unchanged) =================
#define MRM 64
#define SA 264
#define SW 72
#define MS_AH 0
#define MS_AL (MRM * SA * 2)
#define MS_W  (2 * MRM * SA * 2)
#define MS_WPART (256 * SW * 2)
#define MS_TOTAL (MS_W + 4 * MS_WPART)

__device__ __forceinline__ void mma_tiles3(
    const __nv_bfloat16* AH, const __nv_bfloat16* AL,
    const __nv_bfloat16* WH, const __nv_bfloat16* WL,
    int kbase, int wm, int wn, int gid, int tg,
    float (*acc)[8][4])
{
#pragma unroll
    for (int kt = 0; kt < 4; kt++) {
        const int ka = kbase + kt * 16 + tg * 2;
        const int kw = kt * 16 + tg * 2;
        uint32_t ah[2][4], al[2][4];
#pragma unroll
        for (int mf = 0; mf < 2; mf++) {
            const int R = wm * 32 + mf * 16 + gid;
            ah[mf][0] = *(const uint32_t*)(&AH[R * SA + ka]);
            ah[mf][1] = *(const uint32_t*)(&AH[(R + 8) * SA + ka]);
            ah[mf][2] = *(const uint32_t*)(&AH[R * SA + ka + 8]);
            ah[mf][3] = *(const uint32_t*)(&AH[(R + 8) * SA + ka + 8]);
            al[mf][0] = *(const uint32_t*)(&AL[R * SA + ka]);
            al[mf][1] = *(const uint32_t*)(&AL[(R + 8) * SA + ka]);
            al[mf][2] = *(const uint32_t*)(&AL[R * SA + ka + 8]);
            al[mf][3] = *(const uint32_t*)(&AL[(R + 8) * SA + ka + 8]);
        }
#pragma unroll
        for (int nf = 0; nf < 8; nf++) {
            const int C = wn * 64 + nf * 8 + gid;
            uint32_t bh[2], bl[2];
            bh[0] = *(const uint32_t*)(&WH[C * SW + kw]);
            bh[1] = *(const uint32_t*)(&WH[C * SW + kw + 8]);
            bl[0] = *(const uint32_t*)(&WL[C * SW + kw]);
            bl[1] = *(const uint32_t*)(&WL[C * SW + kw + 8]);
#pragma unroll
            for (int mf = 0; mf < 2; mf++) {
                mma_bf16(acc[mf][nf], ah[mf], bh);
                mma_bf16(acc[mf][nf], ah[mf], bl);
                mma_bf16(acc[mf][nf], al[mf], bh);
            }
        }
    }
}

__device__ __forceinline__ void issue_wchunk(
    char* sm, int stage, int tid,
    const __nv_bfloat16* Ghi, const __nv_bfloat16* Glo, int gld, int kofs)
{
    __nv_bfloat16* WH = (__nv_bfloat16*)(sm + MS_W + (stage * 2 + 0) * MS_WPART);
    __nv_bfloat16* WL = (__nv_bfloat16*)(sm + MS_W + (stage * 2 + 1) * MS_WPART);
#pragma unroll
    for (int j = 0; j < 8; j++) {
        int idx = tid + j * 256;
        int n = idx >> 3, kk = (idx & 7) * 8;
        cp16(&WH[n * SW + kk], &Ghi[(size_t)n * gld + kofs + kk]);
        cp16(&WL[n * SW + kk], &Glo[(size_t)n * gld + kofs + kk]);
    }
    cp_commit();
}

__global__ __launch_bounds__(256, 1) void mlp_kernel(
    const float* __restrict__ obs,
    const float* __restrict__ be1,
    const float* __restrict__ be2,
    const float* __restrict__ bq1,
    float* __restrict__ q1e)
{
    extern __shared__ char sm[];
    __nv_bfloat16* AH = (__nv_bfloat16*)(sm + MS_AH);
    __nv_bfloat16* AL = (__nv_bfloat16*)(sm + MS_AL);

    const int tid = threadIdx.x;
    const int lane = tid & 31;
    const int warp = tid >> 5;
    const int gid = lane >> 2;
    const int tg = lane & 3;
    const int wm = warp & 1;
    const int wn = warp >> 1;
    const size_t row0 = (size_t)blockIdx.x * MRM;

    float acc[2][8][4];

    for (int i = tid; i < MRM * OBS; i += 256) {
        int r = i >> 6, c = i & 63;
        float v = obs[(row0 + r) * OBS + c];
        __nv_bfloat16 hi, lo; split_bf16(v, hi, lo);
        AH[r * SA + c] = hi; AL[r * SA + c] = lo;
    }
    {
        __nv_bfloat16* WH = (__nv_bfloat16*)(sm + MS_W + 0 * MS_WPART);
        __nv_bfloat16* WL = (__nv_bfloat16*)(sm + MS_W + 1 * MS_WPART);
#pragma unroll
        for (int j = 0; j < 8; j++) {
            int idx = tid + j * 256;
            int n = idx >> 3, kk = (idx & 7) * 8;
            cp16(&WH[n * SW + kk], &g_W1hi[n * 64 + kk]);
            cp16(&WL[n * SW + kk], &g_W1lo[n * 64 + kk]);
        }
        cp_commit();
    }
    cp_wait<0>();
    __syncthreads();

#pragma unroll
    for (int mf = 0; mf < 2; mf++)
#pragma unroll
        for (int nf = 0; nf < 8; nf++)
#pragma unroll
            for (int q = 0; q < 4; q++) acc[mf][nf][q] = 0.f;
    mma_tiles3(AH, AL,
               (__nv_bfloat16*)(sm + MS_W + 0 * MS_WPART),
               (__nv_bfloat16*)(sm + MS_W + 1 * MS_WPART),
               0, wm, wn, gid, tg, acc);
    __syncthreads();
#pragma unroll
    for (int mf = 0; mf < 2; mf++)
#pragma unroll
        for (int nf = 0; nf < 8; nf++) {
            const int R = wm * 32 + mf * 16 + gid;
            const int C = wn * 64 + nf * 8 + tg * 2;
            float b0 = be1[C], b1 = be1[C + 1];
            float v0 = elu1(acc[mf][nf][0] + b0), v1 = elu1(acc[mf][nf][1] + b1);
            float v2 = elu1(acc[mf][nf][2] + b0), v3 = elu1(acc[mf][nf][3] + b1);
            __nv_bfloat16 h0, l0, h1, l1, h2, l2, h3, l3;
            split_bf16(v0, h0, l0); split_bf16(v1, h1, l1);
            split_bf16(v2, h2, l2); split_bf16(v3, h3, l3);
            *(__nv_bfloat162*)(&AH[R * SA + C])       = __nv_bfloat162(h0, h1);
            *(__nv_bfloat162*)(&AL[R * SA + C])       = __nv_bfloat162(l0, l1);
            *(__nv_bfloat162*)(&AH[(R + 8) * SA + C]) = __nv_bfloat162(h2, h3);
            *(__nv_bfloat162*)(&AL[(R + 8) * SA + C]) = __nv_bfloat162(l2, l3);
        }
    __syncthreads();

    for (int layer = 0; layer < 2; layer++) {
        const __nv_bfloat16* Ghi = layer == 0 ? g_W2hi : g_W3hi;
        const __nv_bfloat16* Glo = layer == 0 ? g_W2lo : g_W3lo;
        const float* bias = layer == 0 ? be2 : bq1;

#pragma unroll
        for (int mf = 0; mf < 2; mf++)
#pragma unroll
            for (int nf = 0; nf < 8; nf++)
#pragma unroll
                for (int q = 0; q < 4; q++) acc[mf][nf][q] = 0.f;

        issue_wchunk(sm, 0, tid, Ghi, Glo, 256, 0);
        for (int c = 0; c < 4; c++) {
            if (c + 1 < 4) {
                issue_wchunk(sm, (c + 1) & 1, tid, Ghi, Glo, 256, (c + 1) * 64);
                cp_wait<1>();
            } else {
                cp_wait<0>();
            }
            __syncthreads();
            mma_tiles3(AH, AL,
                       (__nv_bfloat16*)(sm + MS_W + ((c & 1) * 2 + 0) * MS_WPART),
                       (__nv_bfloat16*)(sm + MS_W + ((c & 1) * 2 + 1) * MS_WPART),
                       c * 64, wm, wn, gid, tg, acc);
            __syncthreads();
        }

        if (layer == 0) {
#pragma unroll
            for (int mf = 0; mf < 2; mf++)
#pragma unroll
                for (int nf = 0; nf < 8; nf++) {
                    const int R = wm * 32 + mf * 16 + gid;
                    const int C = wn * 64 + nf * 8 + tg * 2;
                    float b0 = bias[C], b1 = bias[C + 1];
                    float v0 = elu1(acc[mf][nf][0] + b0), v1 = elu1(acc[mf][nf][1] + b1);
                    float v2 = elu1(acc[mf][nf][2] + b0), v3 = elu1(acc[mf][nf][3] + b1);
                    __nv_bfloat16 h0, l0, h1, l1, h2, l2, h3, l3;
                    split_bf16(v0, h0, l0); split_bf16(v1, h1, l1);
                    split_bf16(v2, h2, l2); split_bf16(v3, h3, l3);
                    *(__nv_bfloat162*)(&AH[R * SA + C])       = __nv_bfloat162(h0, h1);
                    *(__nv_bfloat162*)(&AL[R * SA + C])       = __nv_bfloat162(l0, l1);
                    *(__nv_bfloat162*)(&AH[(R + 8) * SA + C]) = __nv_bfloat162(h2, h3);
                    *(__nv_bfloat162*)(&AL[(R + 8) * SA + C]) = __nv_bfloat162(l2, l3);
                }
            __syncthreads();
        } else {
#pragma unroll
            for (int mf = 0; mf < 2; mf++)
#pragma unroll
                for (int nf = 0; nf < 8; nf++) {
                    const int R = wm * 32 + mf * 16 + gid;
                    const int C = wn * 64 + nf * 8 + tg * 2;
                    float b0 = bias[C], b1 = bias[C + 1];
                    *(float2*)(&q1e[(row0 + R) * 256 + C]) =
                        make_float2(acc[mf][nf][0] + b0, acc[mf][nf][1] + b1);
                    *(float2*)(&q1e[(row0 + R + 8) * 256 + C]) =
                        make_float2(acc[mf][nf][2] + b0, acc[mf][nf][3] + b1);
                }
        }
    }
}

// ================= persistent scan kernel =================
#define NBLK 128
#define WSLICE 80
#define WPAD 776
#define CHK 96
#define NCHK 8
#define APAD 104
#define ACHUNK (128 * APAD)

#define SM_W    0
#define SM_AS   (WSLICE * WPAD * 2)                  // 124160
#define SM_PQ   (SM_AS + 2 * ACHUNK * 2)             // +53248 = 177408
#define SM_ST   (SM_PQ + 2 * 8 * 256 * 4)            // +16384 = 193792
#define SM_ZA   (SM_ST + 8 * 128 * 4)                // +4096  = 197888
#define SM_GI   (SM_ZA + 8 * 40 * 4)                 // +1280  = 199168
#define SM_TOTAL (SM_GI + 3 * 8 * 256 * 4)           // +24576 = 223744

// 16-block group barrier for strip s
__device__ __forceinline__ void group_sync(int s) {
    __syncthreads();
    if (threadIdx.x == 0) {
        __threadfence();
        unsigned* cnt = &g_grp_cnt[s * 32];
        volatile unsigned* gen = &g_grp_gen[s * 32];
        unsigned g = *gen;
        unsigned arrived = atomicAdd(cnt, 1u);
        if (arrived == 15u) {
            *cnt = 0u;
            __threadfence();
            *gen = g + 1u;
        } else {
            while (*gen == g) { }
        }
        __threadfence();
    }
    __syncthreads();
}

__device__ __forceinline__ void issue_achunk(char* smraw, int buf, int tid,
                                             int mbase, int kofs)
{
    __nv_bfloat16* dst = (__nv_bfloat16*)(smraw + SM_AS) + buf * ACHUNK;
#pragma unroll
    for (int j = 0; j < 6; j++) {
        int idx = j * 256 + tid;
        int row = idx / 12, cc = idx % 12;
        cp16(&dst[row * APAD + cc * 8],
             &g_Ah[(size_t)(mbase + row) * 768 + kofs + cc * 8]);
    }
    cp_commit();
}

__global__ __launch_bounds__(256, 1) void scan_kernel(
    const float* __restrict__ q1e,
    const float* __restrict__ noise,
    const float* __restrict__ act,
    const float* __restrict__ bp2,
    const float* __restrict__ bq2,
    const float* __restrict__ bp1,
    const float* __restrict__ bih,
    const float* __restrict__ bhh,
    float* __restrict__ out)
{
    extern __shared__ char smraw[];
    __nv_bfloat16* Wsm = (__nv_bfloat16*)(smraw + SM_W);
    float* PQ  = (float*)(smraw + SM_PQ);
    float* ST  = (float*)(smraw + SM_ST);
    float* ZA  = (float*)(smraw + SM_ZA);
    float* GIs = (float*)(smraw + SM_GI);

    const int tid = threadIdx.x;
    const int blk = blockIdx.x;
    const int lane = tid & 31;
    const int warp = tid >> 5;
    const int gid = lane >> 2;
    const int tg = lane & 3;
    const int wm = warp & 3;
    const int wn = warp >> 2;
    const int bs = blk >> 4;
    const int cs = blk & 15;
    const int mbase = bs * 128;
    const int nbase = cs * WSLICE;
    const int b0 = blk * 8;

    for (int i = tid; i < WSLICE * 768; i += 256) {
        int r = i / 768, k = i - r * 768;
        Wsm[r * WPAD + k] = g_Wcat[(size_t)(nbase + r) * 768 + k];
    }
    __syncthreads();

    for (int t = 0; t < TSTEPS; t++) {
        // ======== phase G: tmp = h_split @ Wslice^T (cp.async k-pipeline) ========
        {
            float acc[2][5][4];
#pragma unroll
            for (int i = 0; i < 2; i++)
#pragma unroll
                for (int j = 0; j < 5; j++)
#pragma unroll
                    for (int q = 0; q < 4; q++) acc[i][j][q] = 0.f;

            issue_achunk(smraw, 0, tid, mbase, 0);
            for (int c = 0; c < NCHK; c++) {
                if (c + 1 < NCHK) {
                    issue_achunk(smraw, (c + 1) & 1, tid, mbase, (c + 1) * CHK);
                    cp_wait<1>();
                } else {
                    cp_wait<0>();
                }
                __syncthreads();
                const __nv_bfloat16* A =
                    (const __nv_bfloat16*)(smraw + SM_AS) + (c & 1) * ACHUNK;
#pragma unroll
                for (int kt = 0; kt < 6; kt++) {
                    const int k0 = kt * 16 + tg * 2;
                    const int kg = c * CHK + kt * 16 + tg * 2;
                    uint32_t af[2][4];
#pragma unroll
                    for (int mf = 0; mf < 2; mf++) {
                        const int r = wm * 32 + mf * 16 + gid;
                        af[mf][0] = *(const uint32_t*)(&A[r * APAD + k0]);
                        af[mf][1] = *(const uint32_t*)(&A[(r + 8) * APAD + k0]);
                        af[mf][2] = *(const uint32_t*)(&A[r * APAD + k0 + 8]);
                        af[mf][3] = *(const uint32_t*)(&A[(r + 8) * APAD + k0 + 8]);
                    }
                    uint32_t bfr[5][2];
#pragma unroll
                    for (int nf = 0; nf < 5; nf++) {
                        const int cc = wn * 40 + nf * 8 + gid;
                        bfr[nf][0] = *(const uint32_t*)(&Wsm[cc * WPAD + kg]);
                        bfr[nf][1] = *(const uint32_t*)(&Wsm[cc * WPAD + kg + 8]);
                    }
#pragma unroll
                    for (int mf = 0; mf < 2; mf++)
#pragma unroll
                        for (int nf = 0; nf < 5; nf++)
                            mma_bf16(acc[mf][nf], af[mf], bfr[nf]);
                }
                __syncthreads();
            }

#pragma unroll
            for (int mf = 0; mf < 2; mf++)
#pragma unroll
                for (int nf = 0; nf < 5; nf++) {
                    const int row = mbase + wm * 32 + mf * 16 + gid;
                    const int col = nbase + wn * 40 + nf * 8 + tg * 2;
                    *(float2*)(&g_tmp[(size_t)row * TMPN + col]) =
                        make_float2(acc[mf][nf][0], acc[mf][nf][1]);
                    *(float2*)(&g_tmp[(size_t)(row + 8) * TMPN + col]) =
                        make_float2(acc[mf][nf][2], acc[mf][nf][3]);
                }
        }

        // prefetch step-local independent data (retires during barrier spin)
        float qv[8];
#pragma unroll
        for (int r = 0; r < 8; r++)
            qv[r] = q1e[((size_t)(b0 + r) * TSTEPS + t) * 256 + tid];
        float epsv = noise[((size_t)t * BSZ + (b0 + (tid >> 5))) * SDIM + (tid & 31)];
        float actv = 0.f;
        if (tid < 8 * ACTD)
            actv = act[((size_t)(b0 + (tid >> 3)) * TSTEPS + t) * ACTD + (tid & 7)];

        group_sync(bs);

        // ======== phase S ========
        // stage 1: biases + ELU
#pragma unroll
        for (int r = 0; r < 8; r++) {
            int b = b0 + r;
            const float* trow = g_tmp + (size_t)b * TMPN;
            PQ[(0 * 8 + r) * 256 + tid] = elu1(trow[tid] + bp1[tid]);
            PQ[(1 * 8 + r) * 256 + tid] = elu1(trow[256 + tid] + qv[r]);
        }
        __syncthreads();

        // stage 2: prior/posterior stats (coalesced packed weights)
        {
            int j = tid & 127;
            int rbase = tid >> 7;
            bool isq = (j >= 64);
            float bb = (isq ? bq2 : bp2)[isq ? j - 64 : j];
            const float* base = PQ + (isq ? 8 * 256 : 0);

            float accm[4] = {0.f, 0.f, 0.f, 0.f};
#pragma unroll 4
            for (int k4 = 0; k4 < 64; k4++) {
                float4 w = g_W2P[k4 * 128 + j];
#pragma unroll
                for (int m = 0; m < 4; m++) {
                    int r = rbase + 2 * m;
                    float4 s = *(const float4*)(base + r * 256 + 4 * k4);
                    accm[m] += s.x * w.x + s.y * w.y + s.z * w.z + s.w * w.w;
                }
            }
#pragma unroll
            for (int m = 0; m < 4; m++) ST[(rbase + 2 * m) * 128 + j] = accm[m] + bb;
        }
        __syncthreads();

        // stage 3: z = qm + qs*eps ; stage act
        {
            int r = tid >> 5, s = tid & 31;
            float qm = ST[r * 128 + 64 + s];
            float qs = expclip(ST[r * 128 + 96 + s]);
            ZA[r * 40 + s] = qm + qs * epsv;
        }
        if (tid < 8 * ACTD) {
            int r = tid >> 3, j = tid & 7;
            ZA[r * 40 + 32 + j] = actv;
        }
        __syncthreads();

        // stage 4a: gi via coalesced packed Wih, one gate at a time (weight reuse x8)
        {
            const int d = tid;
#pragma unroll
            for (int g = 0; g < 3; g++) {
                float gig[8];
                float bv = bih[g * 256 + d];
#pragma unroll
                for (int r = 0; r < 8; r++) gig[r] = bv;
#pragma unroll
                for (int k4 = 0; k4 < 10; k4++) {
                    float4 wv = g_WihP[k4 * 768 + g * 256 + d];
#pragma unroll
                    for (int r = 0; r < 8; r++) {
                        float4 sv = *(const float4*)(&ZA[r * 40 + 4 * k4]);
                        gig[r] = fmaf(sv.x, wv.x,
                                  fmaf(sv.y, wv.y,
                                   fmaf(sv.z, wv.z,
                                    fmaf(sv.w, wv.w, gig[r]))));
                    }
                }
#pragma unroll
                for (int r = 0; r < 8; r++) GIs[(g * 8 + r) * 256 + d] = gig[r];
            }
        }
        // same-thread produce/consume of GIs[.][d] -> no sync needed

        // stage 4b: gates + h update + write h_old + split h_new
#pragma unroll 1
        for (int r = 0; r < 8; r++) {
            int d = tid;
            int b = b0 + r;
            float gir = GIs[(0 * 8 + r) * 256 + d];
            float giu = GIs[(1 * 8 + r) * 256 + d];
            float gin = GIs[(2 * 8 + r) * 256 + d];
            const float* trow = g_tmp + (size_t)b * TMPN + 512;
            float ghr = trow[d]        + bhh[d];
            float ghu = trow[256 + d]  + bhh[256 + d];
            float ghn = trow[512 + d]  + bhh[512 + d];
            float rg = sigmf(gir + ghr);
            float u  = sigmf(giu + ghu);
            float nn = tanhfast(gin + rg * ghn);
            float hold = g_h[(size_t)b * DDIM + d];
            float hnew = (1.f - u) * nn + u * hold;
            out[((size_t)b * TSTEPS + t) * OUTW + d] = hold;
            g_h[(size_t)b * DDIM + d] = hnew;
            __nv_bfloat16 hi, lo; split_bf16(hnew, hi, lo);
            __nv_bfloat16* arow = g_Ah + (size_t)b * 768;
            arow[d] = hi; arow[256 + d] = hi; arow[512 + d] = lo;
        }

        // stage 5: write z, pm, ps, qm, qs
        for (int i = tid; i < 8 * 160; i += 256) {
            int r = i / 160, c = i - r * 160;
            int b = b0 + r;
            float v;
            if (c < 32) {
                v = ZA[r * 40 + c];
            } else {
                v = ST[r * 128 + c - 32];
                if ((c >= 64 && c < 96) || c >= 128) {
                    v = expclip(v);
                }
            }
            out[((size_t)b * TSTEPS + t) * OUTW + 256 + c] = v;
        }
        group_sync(bs);
    }
}

// ---------------- host launch ----------------
extern "C" void kernel_launch(void* const* d_in, const int* in_sizes, int n_in,
                              void* d_out, int out_size)
{
    (void)in_sizes; (void)n_in; (void)out_size;
    const float* obs  = (const float*)d_in[0];
    const float* actp = (const float*)d_in[1];
    const float* noi  = (const float*)d_in[2];
    const float* We1  = (const float*)d_in[3];
    const float* be1  = (const float*)d_in[4];
    const float* We2  = (const float*)d_in[5];
    const float* be2  = (const float*)d_in[6];
    const float* Wih  = (const float*)d_in[7];
    const float* Whh  = (const float*)d_in[8];
    const float* bih  = (const float*)d_in[9];
    const float* bhh  = (const float*)d_in[10];
    const float* Wp1  = (const float*)d_in[11];
    const float* bp1  = (const float*)d_in[12];
    const float* Wp2  = (const float*)d_in[13];
    const float* bp2  = (const float*)d_in[14];
    const float* Wq1  = (const float*)d_in[15];
    const float* bq1  = (const float*)d_in[16];
    const float* Wq2  = (const float*)d_in[17];
    const float* bq2  = (const float*)d_in[18];
    float* out = (float*)d_out;

    float *p_h, *p_q1e;
    __nv_bfloat16* p_Ah;
    cudaGetSymbolAddress((void**)&p_h,   g_h);
    cudaGetSymbolAddress((void**)&p_q1e, g_q1e);
    cudaGetSymbolAddress((void**)&p_Ah,  g_Ah);

    cudaFuncSetAttribute(mlp_kernel,
                         cudaFuncAttributeMaxDynamicSharedMemorySize, MS_TOTAL);
    cudaFuncSetAttribute(scan_kernel,
                         cudaFuncAttributeMaxDynamicSharedMemorySize, SM_TOTAL);

    // launches 1-5: memset, memset, pack_all, packW, mlp -> launch 6 = scan (ncu -s 5 -c 1)
    cudaMemsetAsync(p_h, 0, sizeof(float) * BSZ * DDIM, 0);
    cudaMemsetAsync(p_Ah, 0, sizeof(__nv_bfloat16) * BSZ * 768, 0);

    pack_all_kernel<<<(PKTOT + 255) / 256, 256>>>(Wp1, Wq1, Whh, We1, We2);

    packW_kernel<<<(PW_IH + PW_2 + 255) / 256, 256>>>(Wih, Wp2, Wq2);

    mlp_kernel<<<NROWS / MRM, 256, MS_TOTAL>>>(obs, be1, be2, bq1, p_q1e);

    scan_kernel<<<NBLK, 256, SM_TOTAL>>>(p_q1e, noi, actp,
                                         bp2, bq2, bp1,
                                         bih, bhh, out);
}